// round 1
// baseline (speedup 1.0000x reference)
#include <cuda_runtime.h>
#include <math.h>

#define NUM_CLASSES 3
#define TGT 20
#define BATCH 64
#define BLOCK 512
#define MAXA 9408   // 56*56*3

// partials: [scale][image][3] = obj_loss, cls_loss, loc_loss
__device__ float g_partials[3 * BATCH * 3];

__device__ __forceinline__ float blockReduceSum(float v, float* s_red) {
    int tid = threadIdx.x;
    s_red[tid] = v;
    __syncthreads();
    #pragma unroll
    for (int s = BLOCK / 2; s > 0; s >>= 1) {
        if (tid < s) s_red[tid] += s_red[tid + s];
        __syncthreads();
    }
    float r = s_red[0];
    __syncthreads();
    return r;
}

__global__ __launch_bounds__(BLOCK)
void loss_kernel(const float* __restrict__ pred1, const float* __restrict__ pred2,
                 const float* __restrict__ pred3,
                 const float* __restrict__ an1, const float* __restrict__ an2,
                 const float* __restrict__ an3,
                 const float* __restrict__ tb, const int* __restrict__ tl)
{
    const int b = blockIdx.x;
    const int scale = blockIdx.y;
    const float* pred;
    const float* anchors;
    int f;
    if (scale == 0)      { pred = pred1; anchors = an1; f = 56; }
    else if (scale == 1) { pred = pred2; anchors = an2; f = 28; }
    else                 { pred = pred3; anchors = an3; f = 14; }
    const int fsq = f * f;
    const int A = fsq * 3;

    extern __shared__ unsigned char dyn[];
    float* s_val = (float*)dyn;                              // [MAXA] obj logit -> bce
    unsigned char* s_flag  = (unsigned char*)(dyn + MAXA*4); // [MAXA] bit0=pos bit1=neg
    unsigned char* s_match = s_flag + MAXA;                  // [MAXA] matched target

    __shared__ float s_tbx[TGT][4];
    __shared__ float s_tarea[TGT];
    __shared__ int   s_tlab[TGT];
    __shared__ unsigned long long s_best[TGT];
    __shared__ float s_red[BLOCK];

    const int tid = threadIdx.x;
    if (tid < TGT) {
        const float* p = tb + (size_t)(b * TGT + tid) * 4;
        float x1 = p[0], y1 = p[1], x2 = p[2], y2 = p[3];
        s_tbx[tid][0] = x1; s_tbx[tid][1] = y1; s_tbx[tid][2] = x2; s_tbx[tid][3] = y2;
        s_tarea[tid] = (x2 - x1) * (y2 - y1);
        s_tlab[tid] = tl[b * TGT + tid];
        s_best[tid] = 0ull;
    }
    __syncthreads();

    const float* predb = pred + (size_t)b * 24 * fsq;

    // Phase 1: IoU matching, flags, per-target best anchor, stash obj logits.
    unsigned long long loc[TGT];
    #pragma unroll
    for (int t = 0; t < TGT; t++) loc[t] = 0ull;

    for (int a = tid; a < A; a += BLOCK) {
        float ax1 = anchors[4*a+0], ay1 = anchors[4*a+1];
        float ax2 = anchors[4*a+2], ay2 = anchors[4*a+3];
        float areaA = (ax2 - ax1) * (ay2 - ay1);
        float best = -1.0f; int bi = 0;
        #pragma unroll
        for (int t = 0; t < TGT; t++) {
            float lx = fmaxf(ax1, s_tbx[t][0]);
            float ly = fmaxf(ay1, s_tbx[t][1]);
            float rx = fminf(ax2, s_tbx[t][2]);
            float ry = fminf(ay2, s_tbx[t][3]);
            float w = fmaxf(rx - lx, 0.0f), h = fmaxf(ry - ly, 0.0f);
            float inter = w * h;
            float iou = inter / (areaA + s_tarea[t] - inter + 1e-9f);
            if (iou > best) { best = iou; bi = t; }  // first-occurrence argmax
            unsigned long long pk =
                ((unsigned long long)__float_as_uint(iou) << 32) |
                (unsigned long long)(0xffffffffu - (unsigned)a);
            if (pk > loc[t]) loc[t] = pk;
        }
        unsigned char fl = 0;
        if (best >= 0.5f) fl |= 1;
        if (best <  0.3f) fl |= 2;
        s_flag[a]  = fl;
        s_match[a] = (unsigned char)bi;
        int ai = a % 3, cell = a / 3;
        int w_ = cell % f, h_ = cell / f;
        s_val[a] = predb[(ai * 8 + 4) * fsq + h_ * f + w_];   // obj logit
    }
    #pragma unroll
    for (int t = 0; t < TGT; t++) atomicMax(&s_best[t], loc[t]);
    __syncthreads();

    // Phase 2: forced-positive override (sequential, last target wins).
    if (tid == 0) {
        for (int t = 0; t < TGT; t++) {
            unsigned a = 0xffffffffu - (unsigned)(s_best[t] & 0xffffffffull);
            s_flag[a]  = 1;                 // pos, not neg
            s_match[a] = (unsigned char)t;
        }
    }
    __syncthreads();

    // Phase 3: BCE for all anchors; cls + loc losses for positives.
    float posBce = 0.f, ceSum = 0.f, slSum = 0.f, cntPos = 0.f, cntNeg = 0.f;
    for (int a = tid; a < A; a += BLOCK) {
        float x = s_val[a];
        unsigned char fl = s_flag[a];
        bool pos = (fl & 1) != 0;
        float bce = fmaxf(x, 0.0f) - (pos ? x : 0.0f) + log1pf(expf(-fabsf(x)));
        s_val[a] = bce;
        if (pos) {
            cntPos += 1.0f;
            posBce += bce;
            int t = s_match[a];
            int ai = a % 3, cell = a / 3;
            int w_ = cell % f, h_ = cell / f;
            const float* pb = predb + h_ * f + w_;
            int cs = ai * 8;
            // class CE (log_softmax over 3)
            float c0 = pb[(cs+5)*fsq], c1 = pb[(cs+6)*fsq], c2 = pb[(cs+7)*fsq];
            float m = fmaxf(c0, fmaxf(c1, c2));
            float lse = m + logf(expf(c0-m) + expf(c1-m) + expf(c2-m));
            int tgt = s_tlab[t] - 1;
            float ct = (tgt == 0) ? c0 : ((tgt == 1) ? c1 : c2);
            ceSum += lse - ct;
            // localization smooth-L1
            float ax1 = anchors[4*a+0], ay1 = anchors[4*a+1];
            float ax2 = anchors[4*a+2], ay2 = anchors[4*a+3];
            float aw = ax2 - ax1, ah = ay2 - ay1;
            float acx = (ax1 + ax2) * 0.5f, acy = (ay1 + ay2) * 0.5f;
            float gx1 = s_tbx[t][0], gy1 = s_tbx[t][1];
            float gx2 = s_tbx[t][2], gy2 = s_tbx[t][3];
            float gw = gx2 - gx1, gh = gy2 - gy1;
            float gcx = (gx1 + gx2) * 0.5f, gcy = (gy1 + gy2) * 0.5f;
            float td0 = (gcx - acx) / aw;
            float td1 = (gcy - acy) / ah;
            float td2 = logf(gw / aw);
            float td3 = logf(gh / ah);
            float td[4] = { td0, td1, td2, td3 };
            #pragma unroll
            for (int j = 0; j < 4; j++) {
                float d = fabsf(pb[(cs + j) * fsq] - td[j]);
                slSum += (d < 1.0f) ? 0.5f * d * d : (d - 0.5f);
            }
        } else if (fl & 2) {
            cntNeg += 1.0f;
        }
    }

    float rPos    = blockReduceSum(cntPos, s_red);
    float rNeg    = blockReduceSum(cntNeg, s_red);
    float rPosBce = blockReduceSum(posBce, s_red);
    float rCe     = blockReduceSum(ceSum,  s_red);
    float rSl     = blockReduceSum(slSum,  s_red);

    int np = (int)rPos;
    int nn = (int)rNeg;
    int k = min(3 * np, nn);

    // Phase 4: hard-negative mining via bitwise k-th-largest selection on BCE.
    float negTop = 0.0f;
    if (k > 0) {
        unsigned thr = 0;
        for (int bit = 30; bit >= 0; --bit) {
            unsigned cand = thr | (1u << bit);
            float c = 0.f;
            for (int a = tid; a < A; a += BLOCK)
                if ((s_flag[a] & 2) && __float_as_uint(s_val[a]) >= cand) c += 1.f;
            float tot = blockReduceSum(c, s_red);
            if ((int)tot >= k) thr = cand;
        }
        float sg = 0.f, cg = 0.f;
        for (int a = tid; a < A; a += BLOCK) {
            if (s_flag[a] & 2) {
                unsigned u = __float_as_uint(s_val[a]);
                if (u > thr) { sg += s_val[a]; cg += 1.f; }
            }
        }
        float rsg = blockReduceSum(sg, s_red);
        float rcg = blockReduceSum(cg, s_red);
        negTop = rsg + (float)(k - (int)rcg) * __uint_as_float(thr);
    }

    if (tid == 0) {
        float ol = (rPosBce + negTop) / (float)max(np + k, 1);
        float cl = rCe / (float)max(np, 1);
        float ll = rSl / (float)max(4 * np, 1);
        float* o = &g_partials[(scale * BATCH + b) * 3];
        o[0] = ol; o[1] = cl; o[2] = ll;
    }
}

__global__ void finalize_kernel(float* __restrict__ out) {
    if (threadIdx.x == 0 && blockIdx.x == 0) {
        float s0 = 0.f, s1 = 0.f, s2 = 0.f;
        for (int i = 0; i < 3 * BATCH; i++) {
            s0 += g_partials[i * 3 + 0];
            s1 += g_partials[i * 3 + 1];
            s2 += g_partials[i * 3 + 2];
        }
        float obj = s0 / (float)BATCH;
        float cls = s1 / (float)BATCH;
        float loc = s2 / (float)BATCH;
        out[0] = obj;
        out[1] = cls;
        out[2] = loc;
        out[3] = obj + cls + 2.0f * loc;
    }
}

extern "C" void kernel_launch(void* const* d_in, const int* in_sizes, int n_in,
                              void* d_out, int out_size)
{
    const float* pred1 = (const float*)d_in[0];
    const float* pred2 = (const float*)d_in[1];
    const float* pred3 = (const float*)d_in[2];
    const float* an1   = (const float*)d_in[3];
    const float* an2   = (const float*)d_in[4];
    const float* an3   = (const float*)d_in[5];
    const float* tb    = (const float*)d_in[6];
    const int*   tl    = (const int*)d_in[7];

    const size_t smem = (size_t)MAXA * 4 + (size_t)MAXA * 2;  // 56448 bytes
    cudaFuncSetAttribute(loss_kernel, cudaFuncAttributeMaxDynamicSharedMemorySize,
                         (int)smem);

    dim3 grid(BATCH, 3);
    loss_kernel<<<grid, BLOCK, smem>>>(pred1, pred2, pred3, an1, an2, an3, tb, tl);
    finalize_kernel<<<1, 32>>>((float*)d_out);
}

// round 2
// speedup vs baseline: 1.4130x; 1.4130x over previous
#include <cuda_runtime.h>
#include <math.h>

#define TGT 20
#define BATCH 64
#define BLOCK 512
#define MAXA 9408
#define NBLK (3*BATCH)

struct Sh {
    float tb[TGT][4];
    float tarea[TGT];
    int   tlab[TGT];
    unsigned long long best[TGT];
    float wred[16][8];
    float out[8];
    unsigned warpTot[16];
    unsigned warpSE[16];
    int selBucket;
    unsigned selAbove;
    int isLast;
};

__device__ float g_partials[NBLK * 3];
__device__ unsigned g_done = 0;

template<int N>
__device__ __forceinline__ void blockReduceN(float* v, Sh& sh) {
    int lane = threadIdx.x & 31, wid = threadIdx.x >> 5;
    #pragma unroll
    for (int i = 0; i < N; i++) {
        float x = v[i];
        #pragma unroll
        for (int off = 16; off; off >>= 1) x += __shfl_xor_sync(0xffffffffu, x, off);
        if (lane == 0) sh.wred[wid][i] = x;
    }
    __syncthreads();
    if (threadIdx.x < N) {
        float s = 0.f;
        #pragma unroll
        for (int w = 0; w < 16; w++) s += sh.wred[w][threadIdx.x];
        sh.out[threadIdx.x] = s;
    }
    __syncthreads();
}

template<int F>
__device__ void run_scale(const float* __restrict__ pred,
                          const float* __restrict__ tb,
                          const int* __restrict__ tl,
                          float* __restrict__ out,
                          int b, int scale,
                          unsigned char* dyn, Sh& sh)
{
    constexpr int FSQ = F * F;
    constexpr int A = FSQ * 3;
    constexpr float STRIDE = 448.0f / (float)F;

    float* s_val = (float*)dyn;                      // [MAXA] obj logit -> bce
    unsigned char* s_flag  = dyn + MAXA * 4;         // bit0=pos bit1=neg
    unsigned char* s_match = dyn + MAXA * 5;
    unsigned* hist = (unsigned*)(dyn + MAXA * 6);    // [2048]

    const int tid = threadIdx.x;
    if (tid < TGT) {
        const float* p = tb + (size_t)(b * TGT + tid) * 4;
        float x1 = p[0], y1 = p[1], x2 = p[2], y2 = p[3];
        sh.tb[tid][0] = x1; sh.tb[tid][1] = y1; sh.tb[tid][2] = x2; sh.tb[tid][3] = y2;
        sh.tarea[tid] = (x2 - x1) * (y2 - y1);
        sh.tlab[tid] = tl[b * TGT + tid];
        sh.best[tid] = 0ull;
    }
    __syncthreads();

    const float* predb = pred + (size_t)b * 24 * FSQ;

    // ---------- Phase 1: division-free IoU matching ----------
    float tBI[TGT], tBU[TGT]; int tBA[TGT];
    #pragma unroll
    for (int t = 0; t < TGT; t++) { tBI[t] = -1.f; tBU[t] = 1.f; tBA[t] = 0; }

    for (int cell = tid; cell < FSQ; cell += BLOCK) {
        int row = cell / F, col = cell - row * F;
        float cx = ((float)col + 0.5f) * STRIDE;
        float cy = ((float)row + 0.5f) * STRIDE;
        float bIa[3], bUa[3]; int bta[3];
        #pragma unroll
        for (int ai = 0; ai < 3; ai++) { bIa[ai] = -1.f; bUa[ai] = 1.f; bta[ai] = 0; }

        #pragma unroll
        for (int t = 0; t < TGT; t++) {
            float tx1 = sh.tb[t][0], ty1 = sh.tb[t][1];
            float tx2 = sh.tb[t][2], ty2 = sh.tb[t][3];
            float ta = sh.tarea[t];
            #pragma unroll
            for (int ai = 0; ai < 3; ai++) {
                float half = (1.0f + 0.25f * (float)ai) * STRIDE;
                float lx = fmaxf(cx - half, tx1);
                float ly = fmaxf(cy - half, ty1);
                float rx = fminf(cx + half, tx2);
                float ry = fminf(cy + half, ty2);
                float w = fmaxf(rx - lx, 0.f), h = fmaxf(ry - ly, 0.f);
                float I = w * h;
                float areaA = (2.f * half) * (2.f * half);
                float U = areaA + ta - I;
                if (I * bUa[ai] > bIa[ai] * U) { bIa[ai] = I; bUa[ai] = U; bta[ai] = t; }
                int a = cell * 3 + ai;
                if (I * tBU[t] > tBI[t] * U) { tBI[t] = I; tBU[t] = U; tBA[t] = a; }
            }
        }
        #pragma unroll
        for (int ai = 0; ai < 3; ai++) {
            int a = cell * 3 + ai;
            unsigned char fl = 0;
            if (2.f * bIa[ai] >= bUa[ai]) fl |= 1;       // iou >= 0.5
            if (10.f * bIa[ai] < 3.f * bUa[ai]) fl |= 2; // iou < 0.3
            s_flag[a] = fl;
            s_match[a] = (unsigned char)bta[ai];
            s_val[a] = predb[(ai * 8 + 4) * FSQ + cell]; // obj logit
        }
    }
    #pragma unroll
    for (int t = 0; t < TGT; t++) {
        if (tBI[t] >= 0.f) {
            float iou = tBI[t] / (tBU[t] + 1e-9f);
            unsigned long long key =
                ((unsigned long long)__float_as_uint(iou) << 32) |
                (unsigned long long)(0xffffffffu - (unsigned)tBA[t]);
            atomicMax(&sh.best[t], key);
        }
    }
    __syncthreads();

    // ---------- Phase 2: forced-positive override (last target wins) ----------
    if (tid == 0) {
        #pragma unroll
        for (int t = 0; t < TGT; t++) {
            unsigned a = 0xffffffffu - (unsigned)(sh.best[t] & 0xffffffffull);
            s_flag[a] = 1;
            s_match[a] = (unsigned char)t;
        }
    }
    __syncthreads();

    // ---------- Phase 3: BCE + positive cls/loc losses ----------
    float acc[5] = {0.f, 0.f, 0.f, 0.f, 0.f}; // posBce, ce, sl, cntPos, cntNeg
    for (int cell = tid; cell < FSQ; cell += BLOCK) {
        int row = cell / F, col = cell - row * F;
        float cx = ((float)col + 0.5f) * STRIDE;
        float cy = ((float)row + 0.5f) * STRIDE;
        #pragma unroll
        for (int ai = 0; ai < 3; ai++) {
            int a = cell * 3 + ai;
            float x = s_val[a];
            unsigned char fl = s_flag[a];
            bool pos = (fl & 1) != 0;
            float bce = fmaxf(x, 0.f) - (pos ? x : 0.f) + log1pf(expf(-fabsf(x)));
            s_val[a] = bce;
            if (pos) {
                acc[3] += 1.f; acc[0] += bce;
                int t = s_match[a];
                const float* pb = predb + cell;
                int cs = ai * 8;
                float c0 = pb[(cs + 5) * FSQ], c1 = pb[(cs + 6) * FSQ], c2 = pb[(cs + 7) * FSQ];
                float m = fmaxf(c0, fmaxf(c1, c2));
                float lse = m + logf(expf(c0 - m) + expf(c1 - m) + expf(c2 - m));
                int tg = sh.tlab[t] - 1;
                float ct = (tg == 0) ? c0 : ((tg == 1) ? c1 : c2);
                acc[1] += lse - ct;
                float half = (1.0f + 0.25f * (float)ai) * STRIDE;
                float aw = 2.f * half;
                float gx1 = sh.tb[t][0], gy1 = sh.tb[t][1];
                float gx2 = sh.tb[t][2], gy2 = sh.tb[t][3];
                float gw = gx2 - gx1, gh = gy2 - gy1;
                float gcx = (gx1 + gx2) * 0.5f, gcy = (gy1 + gy2) * 0.5f;
                float td[4] = { (gcx - cx) / aw, (gcy - cy) / aw,
                                logf(gw / aw), logf(gh / aw) };
                #pragma unroll
                for (int j = 0; j < 4; j++) {
                    float d = fabsf(pb[(cs + j) * FSQ] - td[j]);
                    acc[2] += (d < 1.f) ? 0.5f * d * d : d - 0.5f;
                }
            } else if (fl & 2) {
                acc[4] += 1.f;
            }
        }
    }
    blockReduceN<5>(acc, sh);
    float rPosBce = sh.out[0], rCe = sh.out[1], rSl = sh.out[2];
    int np = (int)sh.out[3], nn = (int)sh.out[4];
    int k = min(3 * np, nn);

    // ---------- Phase 4: hard-negative mining via 3-level radix select ----------
    float negTop = 0.f;
    if (k > 0) {
        unsigned prefix = 0;
        int kRem = k;
        const int shifts[3] = {20, 9, 0};
        const int nbitsA[3] = {11, 11, 9};
        #pragma unroll
        for (int lev = 0; lev < 3; lev++) {
            const int shift = shifts[lev];
            const int nbits = nbitsA[lev];
            const int nb = 1 << nbits;
            const unsigned msk = (unsigned)(nb - 1);
            for (int i = tid; i < nb; i += BLOCK) hist[i] = 0;
            __syncthreads();
            const int hiShift = shift + nbits; // <= 31 always
            const unsigned hi = prefix >> hiShift;
            for (int a = tid; a < A; a += BLOCK) {
                if (s_flag[a] & 2) {
                    unsigned u = __float_as_uint(s_val[a]);
                    if ((u >> hiShift) == hi) atomicAdd(&hist[(u >> shift) & msk], 1u);
                }
            }
            __syncthreads();
            const int chunk = (nb >= BLOCK) ? nb / BLOCK : 1;
            int base = tid * chunk;
            unsigned ls = 0;
            if (base < nb)
                for (int j = 0; j < chunk; j++) ls += hist[base + j];
            int lane = tid & 31, wid = tid >> 5;
            unsigned v = ls;
            #pragma unroll
            for (int off = 1; off < 32; off <<= 1) {
                unsigned w2 = __shfl_down_sync(0xffffffffu, v, off);
                if (lane + off < 32) v += w2;
            }
            if (lane == 0) sh.warpTot[wid] = v;
            __syncthreads();
            if (tid < 16) {
                unsigned wv = sh.warpTot[tid];
                unsigned ws = wv;
                #pragma unroll
                for (int off = 1; off < 16; off <<= 1) {
                    unsigned w2 = __shfl_down_sync(0x0000ffffu, ws, off);
                    if (tid + off < 16) ws += w2;
                }
                sh.warpSE[tid] = ws - wv;
            }
            __syncthreads();
            unsigned SE = sh.warpSE[wid] + (v - ls);
            if (SE < (unsigned)kRem && SE + ls >= (unsigned)kRem) {
                unsigned c = SE;
                for (int j = chunk - 1; j >= 0; j--) {
                    unsigned hv = hist[base + j];
                    if (c + hv >= (unsigned)kRem) { sh.selBucket = base + j; sh.selAbove = c; break; }
                    c += hv;
                }
            }
            __syncthreads();
            prefix |= ((unsigned)sh.selBucket) << shift;
            kRem -= (int)sh.selAbove;
            __syncthreads();
        }
        float thrF = __uint_as_float(prefix);
        float sc[2] = {0.f, 0.f};
        for (int a = tid; a < A; a += BLOCK) {
            if (s_flag[a] & 2) {
                unsigned u = __float_as_uint(s_val[a]);
                if (u > prefix) { sc[0] += s_val[a]; sc[1] += 1.f; }
            }
        }
        blockReduceN<2>(sc, sh);
        negTop = sh.out[0] + (float)(k - (int)sh.out[1]) * thrF;
    }

    // ---------- Phase 5: partials + fused last-block finalize ----------
    if (tid == 0) {
        float ol = (rPosBce + negTop) / (float)max(np + k, 1);
        float cl = rCe / (float)max(np, 1);
        float ll = rSl / (float)max(4 * np, 1);
        float* o = &g_partials[(scale * BATCH + b) * 3];
        o[0] = ol; o[1] = cl; o[2] = ll;
        __threadfence();
        unsigned r = atomicAdd(&g_done, 1);
        sh.isLast = (r == NBLK - 1) ? 1 : 0;
    }
    __syncthreads();
    if (sh.isLast) {
        float v[3] = {0.f, 0.f, 0.f};
        for (int i = tid; i < NBLK; i += BLOCK) {
            v[0] += g_partials[i * 3 + 0];
            v[1] += g_partials[i * 3 + 1];
            v[2] += g_partials[i * 3 + 2];
        }
        blockReduceN<3>(v, sh);
        if (tid == 0) {
            float obj = sh.out[0] / (float)BATCH;
            float cls = sh.out[1] / (float)BATCH;
            float loc = sh.out[2] / (float)BATCH;
            out[0] = obj; out[1] = cls; out[2] = loc;
            out[3] = obj + cls + 2.0f * loc;
            g_done = 0;  // reset for next graph replay
        }
    }
}

__global__ __launch_bounds__(BLOCK)
void loss_kernel(const float* __restrict__ pred1, const float* __restrict__ pred2,
                 const float* __restrict__ pred3,
                 const float* __restrict__ tb, const int* __restrict__ tl,
                 float* __restrict__ out)
{
    extern __shared__ unsigned char dyn[];
    __shared__ Sh sh;
    int b = blockIdx.x, scale = blockIdx.y;
    if (scale == 0)      run_scale<56>(pred1, tb, tl, out, b, 0, dyn, sh);
    else if (scale == 1) run_scale<28>(pred2, tb, tl, out, b, 1, dyn, sh);
    else                 run_scale<14>(pred3, tb, tl, out, b, 2, dyn, sh);
}

extern "C" void kernel_launch(void* const* d_in, const int* in_sizes, int n_in,
                              void* d_out, int out_size)
{
    const float* pred1 = (const float*)d_in[0];
    const float* pred2 = (const float*)d_in[1];
    const float* pred3 = (const float*)d_in[2];
    const float* tb    = (const float*)d_in[6];
    const int*   tl    = (const int*)d_in[7];

    const int smem = MAXA * 6 + 2048 * 4;  // 64640 bytes
    cudaFuncSetAttribute(loss_kernel, cudaFuncAttributeMaxDynamicSharedMemorySize, smem);

    dim3 grid(BATCH, 3);
    loss_kernel<<<grid, BLOCK, smem>>>(pred1, pred2, pred3, tb, tl, (float*)d_out);
}

// round 3
// speedup vs baseline: 3.0910x; 2.1875x over previous
#include <cuda_runtime.h>
#include <math.h>

#define TGT 20
#define BATCH 64
#define BLOCK 1024
#define NWARP (BLOCK / 32)
#define MAXA 9408
#define NBLK (3 * BATCH)

// dynamic smem layout (bytes)
#define OFF_KEY  0                       // ull[MAXA]   75264
#define OFF_BCE  75264                   // f32[MAXA]   37632
#define OFF_FM   112896                  // u8[MAXA]     9408  (1 = neg)
#define OFF_OV   122304                  // u8[MAXA]     9408  (override t or 0xff)
#define OFF_HIST 131712                  // u32[2048]    8192
#define SMEM_BYTES 139904

struct Sh {
    float tb[TGT][4];
    float tarea[TGT];
    int   tlab[TGT];
    unsigned long long best[TGT];
    float wred[NWARP][8];
    float out[8];
    unsigned warpTot[NWARP];
    unsigned warpSE[NWARP];
    int selBucket;
    unsigned selAbove;
    int isLast;
};

__device__ float g_partials[NBLK * 3];
__device__ unsigned g_done = 0;

template<int N>
__device__ __forceinline__ void blockReduceN(float* v, Sh& sh) {
    int lane = threadIdx.x & 31, wid = threadIdx.x >> 5;
    #pragma unroll
    for (int i = 0; i < N; i++) {
        float x = v[i];
        #pragma unroll
        for (int off = 16; off; off >>= 1) x += __shfl_xor_sync(0xffffffffu, x, off);
        if (lane == 0) sh.wred[wid][i] = x;
    }
    __syncthreads();
    if (threadIdx.x < N) {
        float s = 0.f;
        #pragma unroll
        for (int w = 0; w < NWARP; w++) s += sh.wred[w][threadIdx.x];
        sh.out[threadIdx.x] = s;
    }
    __syncthreads();
}

template<int F>
__device__ void run_scale(const float* __restrict__ pred,
                          const float* __restrict__ tb,
                          const int* __restrict__ tl,
                          float* __restrict__ out,
                          int b, int scale,
                          unsigned char* dyn, Sh& sh)
{
    constexpr int FSQ = F * F;
    constexpr int A = FSQ * 3;
    constexpr float STRIDE = 448.0f / (float)F;

    unsigned long long* s_key = (unsigned long long*)(dyn + OFF_KEY);
    float* s_bce = (float*)(dyn + OFF_BCE);
    unsigned char* s_fm = dyn + OFF_FM;
    unsigned char* s_ov = dyn + OFF_OV;
    unsigned* hist = (unsigned*)(dyn + OFF_HIST);

    const int tid = threadIdx.x;
    if (tid < TGT) {
        const float* p = tb + (size_t)(b * TGT + tid) * 4;
        float x1 = p[0], y1 = p[1], x2 = p[2], y2 = p[3];
        sh.tb[tid][0] = x1; sh.tb[tid][1] = y1; sh.tb[tid][2] = x2; sh.tb[tid][3] = y2;
        sh.tarea[tid] = (x2 - x1) * (y2 - y1);
        sh.tlab[tid] = tl[b * TGT + tid];
        sh.best[tid] = 0ull;
    }
    for (int a = tid; a < A; a += BLOCK) { s_key[a] = 0ull; s_ov[a] = 0xff; }
    __syncthreads();

    const float* predb = pred + (size_t)b * 24 * FSQ;

    // ---------- Phase 1: target-centric sparse IoU scatter ----------
    const float half3 = 1.5f * STRIDE;
    for (int t = 0; t < TGT; t++) {
        float tx1 = sh.tb[t][0], ty1 = sh.tb[t][1];
        float tx2 = sh.tb[t][2], ty2 = sh.tb[t][3];
        float ta = sh.tarea[t];
        int c0 = max(0, (int)floorf((tx1 - half3) / STRIDE - 0.5f));
        int c1 = min(F - 1, (int)ceilf((tx2 + half3) / STRIDE - 0.5f));
        int r0 = max(0, (int)floorf((ty1 - half3) / STRIDE - 0.5f));
        int r1 = min(F - 1, (int)ceilf((ty2 + half3) / STRIDE - 0.5f));
        if (c1 < c0 || r1 < r0) continue;
        int w = c1 - c0 + 1, hh = r1 - r0 + 1;
        int n = w * hh * 3;
        unsigned long long bt = 0ull;
        for (int i = tid; i < n; i += BLOCK) {
            int ci = i / 3, ai = i - 3 * ci;
            int rr = ci / w, cc = ci - rr * w;
            int r = r0 + rr, c = c0 + cc;
            float cx = ((float)c + 0.5f) * STRIDE;
            float cy = ((float)r + 0.5f) * STRIDE;
            float half = (1.0f + 0.25f * (float)ai) * STRIDE;
            float lx = fmaxf(cx - half, tx1);
            float ly = fmaxf(cy - half, ty1);
            float rx = fminf(cx + half, tx2);
            float ry = fminf(cy + half, ty2);
            float iw = rx - lx, ih = ry - ly;
            if (iw > 0.f && ih > 0.f) {
                float I = iw * ih;
                float areaA = (2.f * half) * (2.f * half);
                float U = areaA + ta - I;
                float iou = I / (U + 1e-9f);
                unsigned ib = __float_as_uint(iou);
                int a = (r * F + c) * 3 + ai;
                atomicMax(&s_key[a],
                    ((unsigned long long)ib << 32) | (unsigned long long)(255 - t));
                unsigned long long pk =
                    ((unsigned long long)ib << 32) |
                    (unsigned long long)(0xffffffffu - (unsigned)a);
                if (pk > bt) bt = pk;
            }
        }
        #pragma unroll
        for (int off = 16; off; off >>= 1) {
            unsigned long long o = __shfl_down_sync(0xffffffffu, bt, off);
            if (o > bt) bt = o;
        }
        if ((tid & 31) == 0 && bt) atomicMax(&sh.best[t], bt);
    }
    __syncthreads();

    // ---------- Phase 2: forced-positive override (last target wins) ----------
    if (tid == 0) {
        #pragma unroll
        for (int t = 0; t < TGT; t++) {
            if (sh.best[t]) {
                unsigned a = 0xffffffffu - (unsigned)(sh.best[t] & 0xffffffffull);
                s_ov[a] = (unsigned char)t;
            }
        }
    }
    __syncthreads();

    // ---------- Phase 3: BCE + positive cls/loc losses ----------
    float acc[5] = {0.f, 0.f, 0.f, 0.f, 0.f}; // posBce, ce, sl, cntPos, cntNeg
    for (int cell = tid; cell < FSQ; cell += BLOCK) {
        int row = cell / F, col = cell - row * F;
        float cx = ((float)col + 0.5f) * STRIDE;
        float cy = ((float)row + 0.5f) * STRIDE;
        #pragma unroll
        for (int ai = 0; ai < 3; ai++) {
            int a = cell * 3 + ai;
            unsigned long long key = s_key[a];
            float iou = __uint_as_float((unsigned)(key >> 32));
            unsigned char ov = s_ov[a];
            bool forced = (ov != 0xff);
            bool pos = forced || (iou >= 0.5f);
            bool neg = (!forced) && (iou < 0.3f);
            float x = predb[(ai * 8 + 4) * FSQ + cell];
            float e = __expf(-fabsf(x));
            float bce = fmaxf(x, 0.f) - (pos ? x : 0.f) + __logf(1.f + e);
            s_bce[a] = bce;
            s_fm[a] = neg ? 1 : 0;
            if (pos) {
                acc[3] += 1.f; acc[0] += bce;
                int t = forced ? (int)ov : (255 - (int)(key & 0xffull));
                const float* pb = predb + cell;
                int cs = ai * 8;
                float c0v = pb[(cs + 5) * FSQ], c1v = pb[(cs + 6) * FSQ], c2v = pb[(cs + 7) * FSQ];
                float m = fmaxf(c0v, fmaxf(c1v, c2v));
                float lse = m + logf(expf(c0v - m) + expf(c1v - m) + expf(c2v - m));
                int tg = sh.tlab[t] - 1;
                float ct = (tg == 0) ? c0v : ((tg == 1) ? c1v : c2v);
                acc[1] += lse - ct;
                float half = (1.0f + 0.25f * (float)ai) * STRIDE;
                float aw = 2.f * half;
                float gx1 = sh.tb[t][0], gy1 = sh.tb[t][1];
                float gx2 = sh.tb[t][2], gy2 = sh.tb[t][3];
                float gw = gx2 - gx1, gh = gy2 - gy1;
                float gcx = (gx1 + gx2) * 0.5f, gcy = (gy1 + gy2) * 0.5f;
                float td[4] = { (gcx - cx) / aw, (gcy - cy) / aw,
                                logf(gw / aw), logf(gh / aw) };
                #pragma unroll
                for (int j = 0; j < 4; j++) {
                    float d = fabsf(pb[(cs + j) * FSQ] - td[j]);
                    acc[2] += (d < 1.f) ? 0.5f * d * d : d - 0.5f;
                }
            } else if (neg) {
                acc[4] += 1.f;
            }
        }
    }
    blockReduceN<5>(acc, sh);
    float rPosBce = sh.out[0], rCe = sh.out[1], rSl = sh.out[2];
    int np = (int)sh.out[3], nn = (int)sh.out[4];
    int k = min(3 * np, nn);

    // ---------- Phase 4: hard-negative mining via 3-level radix select ----------
    float negTop = 0.f;
    if (k > 0) {
        unsigned prefix = 0;
        int kRem = k;
        const int shifts[3] = {20, 9, 0};
        const int nbitsA[3] = {11, 11, 9};
        #pragma unroll
        for (int lev = 0; lev < 3; lev++) {
            const int shift = shifts[lev];
            const int nbits = nbitsA[lev];
            const int nb = 1 << nbits;
            const unsigned msk = (unsigned)(nb - 1);
            for (int i = tid; i < nb; i += BLOCK) hist[i] = 0;
            __syncthreads();
            const int hiShift = shift + nbits;
            const unsigned hi = prefix >> hiShift;
            for (int a = tid; a < A; a += BLOCK) {
                if (s_fm[a]) {
                    unsigned u = __float_as_uint(s_bce[a]);
                    if ((u >> hiShift) == hi) atomicAdd(&hist[(u >> shift) & msk], 1u);
                }
            }
            __syncthreads();
            const int chunk = (nb >= BLOCK) ? nb / BLOCK : 1;
            int base = tid * chunk;
            unsigned ls = 0;
            if (base < nb)
                for (int j = 0; j < chunk; j++) ls += hist[base + j];
            int lane = tid & 31, wid = tid >> 5;
            unsigned v = ls;
            #pragma unroll
            for (int off = 1; off < 32; off <<= 1) {
                unsigned w2 = __shfl_down_sync(0xffffffffu, v, off);
                if (lane + off < 32) v += w2;
            }
            if (lane == 0) sh.warpTot[wid] = v;
            __syncthreads();
            if (tid < NWARP) {
                unsigned wv = sh.warpTot[tid];
                unsigned ws = wv;
                #pragma unroll
                for (int off = 1; off < NWARP; off <<= 1) {
                    unsigned w2 = __shfl_down_sync(0xffffffffu, ws, off);
                    if (tid + off < NWARP) ws += w2;
                }
                sh.warpSE[tid] = ws - wv;
            }
            __syncthreads();
            unsigned SE = sh.warpSE[wid] + (v - ls);
            if (base < nb && SE < (unsigned)kRem && SE + ls >= (unsigned)kRem) {
                unsigned c = SE;
                for (int j = chunk - 1; j >= 0; j--) {
                    unsigned hv = hist[base + j];
                    if (c + hv >= (unsigned)kRem) { sh.selBucket = base + j; sh.selAbove = c; break; }
                    c += hv;
                }
            }
            __syncthreads();
            prefix |= ((unsigned)sh.selBucket) << shift;
            kRem -= (int)sh.selAbove;
            __syncthreads();
        }
        float thrF = __uint_as_float(prefix);
        float sc[2] = {0.f, 0.f};
        for (int a = tid; a < A; a += BLOCK) {
            if (s_fm[a]) {
                unsigned u = __float_as_uint(s_bce[a]);
                if (u > prefix) { sc[0] += s_bce[a]; sc[1] += 1.f; }
            }
        }
        blockReduceN<2>(sc, sh);
        negTop = sh.out[0] + (float)(k - (int)sh.out[1]) * thrF;
    }

    // ---------- Phase 5: partials + fused last-block finalize ----------
    if (tid == 0) {
        float ol = (rPosBce + negTop) / (float)max(np + k, 1);
        float cl = rCe / (float)max(np, 1);
        float ll = rSl / (float)max(4 * np, 1);
        float* o = &g_partials[(scale * BATCH + b) * 3];
        o[0] = ol; o[1] = cl; o[2] = ll;
        __threadfence();
        unsigned r = atomicAdd(&g_done, 1);
        sh.isLast = (r == NBLK - 1) ? 1 : 0;
    }
    __syncthreads();
    if (sh.isLast) {
        float v[3] = {0.f, 0.f, 0.f};
        for (int i = tid; i < NBLK; i += BLOCK) {
            v[0] += g_partials[i * 3 + 0];
            v[1] += g_partials[i * 3 + 1];
            v[2] += g_partials[i * 3 + 2];
        }
        blockReduceN<3>(v, sh);
        if (tid == 0) {
            float obj = sh.out[0] / (float)BATCH;
            float cls = sh.out[1] / (float)BATCH;
            float loc = sh.out[2] / (float)BATCH;
            out[0] = obj; out[1] = cls; out[2] = loc;
            out[3] = obj + cls + 2.0f * loc;
            g_done = 0;  // reset for next graph replay
        }
    }
}

__global__ __launch_bounds__(BLOCK)
void loss_kernel(const float* __restrict__ pred1, const float* __restrict__ pred2,
                 const float* __restrict__ pred3,
                 const float* __restrict__ tb, const int* __restrict__ tl,
                 float* __restrict__ out)
{
    extern __shared__ unsigned char dyn[];
    __shared__ Sh sh;
    int b = blockIdx.x, scale = blockIdx.y;
    if (scale == 0)      run_scale<56>(pred1, tb, tl, out, b, 0, dyn, sh);
    else if (scale == 1) run_scale<28>(pred2, tb, tl, out, b, 1, dyn, sh);
    else                 run_scale<14>(pred3, tb, tl, out, b, 2, dyn, sh);
}

extern "C" void kernel_launch(void* const* d_in, const int* in_sizes, int n_in,
                              void* d_out, int out_size)
{
    const float* pred1 = (const float*)d_in[0];
    const float* pred2 = (const float*)d_in[1];
    const float* pred3 = (const float*)d_in[2];
    const float* tb    = (const float*)d_in[6];
    const int*   tl    = (const int*)d_in[7];

    cudaFuncSetAttribute(loss_kernel, cudaFuncAttributeMaxDynamicSharedMemorySize,
                         SMEM_BYTES);

    dim3 grid(BATCH, 3);
    loss_kernel<<<grid, BLOCK, SMEM_BYTES>>>(pred1, pred2, pred3, tb, tl, (float*)d_out);
}